// round 8
// baseline (speedup 1.0000x reference)
#include <cuda_runtime.h>
#include <cuda_bf16.h>
#include <cstdint>

// ---------------------------------------------------------------------------
// MultiScaleHeteroConv: 3 relations x 2 scales GAT + gated fusion.
// R7: GEMM reverted to the R3 fp32 f32x2 path (HMMA kernel kills the
//     container; quarantined). Edge path rebuilt as CSR gather:
//     histogram+scan+scatter once per relation, then warp-per-dst gather
//     with fused softmax-normalize + bias + relation-gate -> no atomics,
//     no TMP/DEN memsets, norm_add_k deleted.
// ---------------------------------------------------------------------------

#define NN_MAX 100000
#define E_MAX  1000000
#define HIDD   128
#define NHEAD  4

// -------------------- scratch (static device globals; no allocs) -----------
__device__ float g_HS  [(size_t)NN_MAX * HIDD];
__device__ float g_TMP [(size_t)NN_MAX * HIDD];
__device__ float g_LOCU[(size_t)NN_MAX * HIDD];
__device__ float g_GLBU[(size_t)NN_MAX * HIDD];
__device__ float g_LOCI[(size_t)NN_MAX * HIDD];
__device__ float g_GLBI[(size_t)NN_MAX * HIDD];
__device__ float g_FUS [(size_t)NN_MAX * HIDD];
__device__ float g_AS  [(size_t)NN_MAX * NHEAD];
__device__ float g_AD  [(size_t)NN_MAX * NHEAD];
__device__ int   g_DEG [NN_MAX];                 // degree / scatter cursor
__device__ int   g_OFF [3 * (NN_MAX + 1)];       // CSR offsets per relation
__device__ int   g_CSRC[3 * E_MAX];              // CSR src lists per relation

// -------------------- f32x2 helpers ----------------------------------------
__device__ __forceinline__ unsigned long long pack2(float lo, float hi) {
    unsigned long long d;
    asm("mov.b64 %0, {%1, %2};" : "=l"(d) : "r"(__float_as_uint(lo)), "r"(__float_as_uint(hi)));
    return d;
}
__device__ __forceinline__ void unpack2(unsigned long long d, float& lo, float& hi) {
    unsigned int a, b;
    asm("mov.b64 {%0, %1}, %2;" : "=r"(a), "=r"(b) : "l"(d));
    lo = __uint_as_float(a); hi = __uint_as_float(b);
}
#define FMA2(acc, a, b) \
    asm("fma.rn.f32x2 %0, %1, %2, %0;" : "+l"(acc) : "l"(a), "l"(b))

// -------------------- GEMM: C[M,128] = A[M,128] @ B[128,128] (R3, passing) --
__global__ __launch_bounds__(256, 1) void gemm128(
    const float* __restrict__ A, const float* __restrict__ B,
    float* __restrict__ Cw, int M,
    const float* __restrict__ bias, int beta, int act,
    const float* __restrict__ att, float* __restrict__ aout,
    const float* __restrict__ loc, const float* __restrict__ glb,
    float* __restrict__ fus)
{
    extern __shared__ float sm[];
    float* As = sm;               // [128][128]
    float* Bs = sm + 128 * 128;   // [128][128]
    int t  = threadIdx.x;
    int m0 = blockIdx.x * 128;

    const float4* B4 = (const float4*)B;
    float4* Bs4 = (float4*)Bs;
#pragma unroll
    for (int i = 0; i < 16; i++) Bs4[t + i * 256] = B4[t + i * 256];

    float4* As4 = (float4*)As;
#pragma unroll
    for (int i = 0; i < 16; i++) {
        int idx = t + i * 256;
        int row = idx >> 5;
        float4 v = make_float4(0.f, 0.f, 0.f, 0.f);
        if (m0 + row < M) v = ((const float4*)A)[(size_t)(m0 + row) * 32 + (idx & 31)];
        As4[idx] = v;
    }
    __syncthreads();

    int tx = t & 15, ty = t >> 4;
    unsigned long long acc[8][4];
#pragma unroll
    for (int r = 0; r < 8; r++)
#pragma unroll
        for (int c = 0; c < 4; c++) acc[r][c] = 0ull;

    const float* ap = As + (ty * 8) * 128;
    const float* bp = Bs + tx * 8;

#pragma unroll 2
    for (int k0 = 0; k0 < 128; k0 += 4) {
        float4 a4[8];
#pragma unroll
        for (int r = 0; r < 8; r++) a4[r] = *(const float4*)(ap + r * 128 + k0);
#pragma unroll
        for (int kk = 0; kk < 4; kk++) {
            const float* brow = bp + (k0 + kk) * 128;
            ulonglong2 p0 = *(const ulonglong2*)brow;
            ulonglong2 p1 = *(const ulonglong2*)(brow + 4);
            unsigned long long bq[4] = {p0.x, p0.y, p1.x, p1.y};
#pragma unroll
            for (int r = 0; r < 8; r++) {
                float av = (kk == 0) ? a4[r].x : (kk == 1) ? a4[r].y
                         : (kk == 2) ? a4[r].z : a4[r].w;
                unsigned long long ap2 = pack2(av, av);
#pragma unroll
                for (int c = 0; c < 4; c++) FMA2(acc[r][c], ap2, bq[c]);
            }
        }
    }

    float at[8];
    if (att) {
#pragma unroll
        for (int c = 0; c < 8; c++) at[c] = att[tx * 8 + c];
    }
#pragma unroll
    for (int r = 0; r < 8; r++) {
        int row = m0 + ty * 8 + r;
        bool valid = row < M;
        size_t base = (size_t)row * 128 + tx * 8;
        float v[8];
#pragma unroll
        for (int c = 0; c < 4; c++) unpack2(acc[r][c], v[2 * c], v[2 * c + 1]);
        if (beta && valid) {
            float4 o0 = *(const float4*)(Cw + base);
            float4 o1 = *(const float4*)(Cw + base + 4);
            v[0] += o0.x; v[1] += o0.y; v[2] += o0.z; v[3] += o0.w;
            v[4] += o1.x; v[5] += o1.y; v[6] += o1.z; v[7] += o1.w;
        }
        if (bias) {
#pragma unroll
            for (int c = 0; c < 8; c++) v[c] += bias[tx * 8 + c];
        }
        if (act) {
#pragma unroll
            for (int c = 0; c < 8; c++) v[c] = 1.f / (1.f + __expf(-v[c]));
        }
        if (fus) {
            if (valid) {
                float4 l0 = *(const float4*)(loc + base);
                float4 l1 = *(const float4*)(loc + base + 4);
                float4 g0 = *(const float4*)(glb + base);
                float4 g1 = *(const float4*)(glb + base + 4);
                float lv[8] = {l0.x, l0.y, l0.z, l0.w, l1.x, l1.y, l1.z, l1.w};
                float gv[8] = {g0.x, g0.y, g0.z, g0.w, g1.x, g1.y, g1.z, g1.w};
                float o[8];
#pragma unroll
                for (int c = 0; c < 8; c++) o[c] = v[c] * lv[c] + (1.f - v[c]) * gv[c];
                *(float4*)(fus + base)     = make_float4(o[0], o[1], o[2], o[3]);
                *(float4*)(fus + base + 4) = make_float4(o[4], o[5], o[6], o[7]);
            }
        } else if (Cw && valid) {
            *(float4*)(Cw + base)     = make_float4(v[0], v[1], v[2], v[3]);
            *(float4*)(Cw + base + 4) = make_float4(v[4], v[5], v[6], v[7]);
        }
        if (att) {
            float s = 0.f;
#pragma unroll
            for (int c = 0; c < 8; c++) s = fmaf(v[c], at[c], s);
            s += __shfl_xor_sync(0xffffffffu, s, 1);
            s += __shfl_xor_sync(0xffffffffu, s, 2);
            if ((tx & 3) == 0 && valid) aout[(size_t)row * 4 + (tx >> 2)] = s;
        }
    }
}

// -------------------- CSR build ---------------------------------------------
__global__ void hist_k(const int* __restrict__ dst, int nE, int* __restrict__ deg)
{
    int e = blockIdx.x * blockDim.x + threadIdx.x;
    if (e < nE) atomicAdd(&deg[dst[e]], 1);
}

// single-block exclusive scan of deg[0..n) -> off[0..n], off[n]=total
__global__ __launch_bounds__(1024) void scan_k(const int* __restrict__ deg,
                                               int* __restrict__ off, int n)
{
    __shared__ int ssum[1024];
    int t = threadIdx.x;
    int chunk = (n + 1023) / 1024;
    int start = t * chunk;
    int end   = start + chunk; if (end > n) end = n;
    int s = 0;
    for (int i = start; i < end; i++) s += deg[i];
    ssum[t] = s;
    __syncthreads();
    for (int o = 1; o < 1024; o <<= 1) {
        int u = (t >= o) ? ssum[t - o] : 0;
        __syncthreads();
        ssum[t] += u;
        __syncthreads();
    }
    int running = (t == 0) ? 0 : ssum[t - 1];
    for (int i = start; i < end; i++) { off[i] = running; running += deg[i]; }
    if (t == 1023) off[n] = ssum[1023];
}

__global__ void scatter_k(const int* __restrict__ src, const int* __restrict__ dst,
                          int nE, int* __restrict__ cur, int* __restrict__ csrc)
{
    int e = blockIdx.x * blockDim.x + threadIdx.x;
    if (e >= nE) return;
    int pos = atomicAdd(&cur[dst[e]], 1);
    csrc[pos] = src[e];
}

// -------------------- gather: one warp per dst node -------------------------
// acc = sum_e exp(lrelu(a_s[src]+a_d[d])) * HS[src];  den likewise.
// out = coef * (acc/den + bias)  (+= target if beta). No atomics.
__global__ __launch_bounds__(256) void gat_gather_k(
    const int* __restrict__ off, const int* __restrict__ csrc,
    const float* __restrict__ a_s, const float* __restrict__ a_d,
    const float* __restrict__ HS, const float* __restrict__ bias,
    float* __restrict__ target, int beta,
    const float* __restrict__ gates, int gidx,
    int selfloop, float slope, int n)
{
    int w = (blockIdx.x * blockDim.x + threadIdx.x) >> 5;
    int lane = threadIdx.x & 31;
    if (w >= n) return;
    int d = w, h = lane >> 3;

    float adh = a_d[(size_t)d * 4 + h];
    float a0 = 0.f, a1 = 0.f, a2 = 0.f, a3 = 0.f, den = 0.f;

    int i0 = off[d], i1 = off[d + 1];
    for (int i = i0; i < i1; i++) {
        int s = csrc[i];
        float e = a_s[(size_t)s * 4 + h] + adh;
        e = e > 0.f ? e : e * slope;
        float wt = __expf(e);
        float4 hv = *(const float4*)(HS + (size_t)s * HIDD + lane * 4);
        a0 = fmaf(wt, hv.x, a0); a1 = fmaf(wt, hv.y, a1);
        a2 = fmaf(wt, hv.z, a2); a3 = fmaf(wt, hv.w, a3);
        den += wt;
    }
    if (selfloop) {
        float e = a_s[(size_t)d * 4 + h] + adh;
        e = e > 0.f ? e : e * slope;
        float wt = __expf(e);
        float4 hv = *(const float4*)(HS + (size_t)d * HIDD + lane * 4);
        a0 = fmaf(wt, hv.x, a0); a1 = fmaf(wt, hv.y, a1);
        a2 = fmaf(wt, hv.z, a2); a3 = fmaf(wt, hv.w, a3);
        den += wt;
    }

    float coef = 1.f;
    if (gates) {
        float g0 = gates[0], g1 = gates[1];
        float mx = fmaxf(g0, g1);
        float e0 = __expf(g0 - mx), e1 = __expf(g1 - mx);
        coef = (gidx == 0 ? e0 : e1) / (e0 + e1);
    }
    float inv = 1.f / (den + 1e-16f);
    float4 bv = *(const float4*)(bias + lane * 4);
    float4 o;
    o.x = coef * (a0 * inv + bv.x);
    o.y = coef * (a1 * inv + bv.y);
    o.z = coef * (a2 * inv + bv.z);
    o.w = coef * (a3 * inv + bv.w);
    float* tp = target + (size_t)d * HIDD + lane * 4;
    if (beta) {
        float4 old = *(const float4*)tp;
        o.x += old.x; o.y += old.y; o.z += old.z; o.w += old.w;
    }
    *(float4*)tp = o;
}

// ---------------------------------------------------------------------------
extern "C" void kernel_launch(void* const* d_in, const int* in_sizes, int n_in,
                              void* d_out, int out_size)
{
    const float* x_user = (const float*)d_in[0];
    const float* x_item = (const float*)d_in[1];
    const float* Wsl    = (const float*)d_in[2];
    const float* Wdl    = (const float*)d_in[3];
    const float* asl    = (const float*)d_in[4];
    const float* adl    = (const float*)d_in[5];
    const float* bl     = (const float*)d_in[6];
    const float* Wsg    = (const float*)d_in[7];
    const float* Wdg    = (const float*)d_in[8];
    const float* asg    = (const float*)d_in[9];
    const float* adg    = (const float*)d_in[10];
    const float* bg     = (const float*)d_in[11];
    const float* gW     = (const float*)d_in[12];
    const float* gb     = (const float*)d_in[13];
    const float* oW     = (const float*)d_in[14];
    const float* rg     = (const float*)d_in[15];
    const int*   ei_buys    = (const int*)d_in[16];
    const int*   ei_rev     = (const int*)d_in[17];
    const int*   ei_follows = (const int*)d_in[18];

    int Nn = in_sizes[0] / HIDD;
    int E  = in_sizes[16] / 2;

    float *HS, *TMP, *LOCU, *GLBU, *LOCI, *GLBI, *FUS, *AS, *AD;
    int *DEG, *OFF, *CSRC;
    cudaGetSymbolAddress((void**)&HS,  g_HS);
    cudaGetSymbolAddress((void**)&TMP, g_TMP);
    cudaGetSymbolAddress((void**)&LOCU,g_LOCU);
    cudaGetSymbolAddress((void**)&GLBU,g_GLBU);
    cudaGetSymbolAddress((void**)&LOCI,g_LOCI);
    cudaGetSymbolAddress((void**)&GLBI,g_GLBI);
    cudaGetSymbolAddress((void**)&FUS, g_FUS);
    cudaGetSymbolAddress((void**)&AS,  g_AS);
    cudaGetSymbolAddress((void**)&AD,  g_AD);
    cudaGetSymbolAddress((void**)&DEG, g_DEG);
    cudaGetSymbolAddress((void**)&OFF, g_OFF);
    cudaGetSymbolAddress((void**)&CSRC,g_CSRC);

    const int GEMM_SMEM = (128 * 128 + 128 * 128) * (int)sizeof(float);  // 128KB
    cudaFuncSetAttribute(gemm128, cudaFuncAttributeMaxDynamicSharedMemorySize, GEMM_SMEM);

    int gemm_blocks = (Nn + 127) / 128;
    int eg_blocks   = (E + 255) / 256;
    int gw_blocks   = (Nn * 32 + 255) / 256;   // 1 warp per node, 8 warps/block

    // ---- build 3 CSRs (relation edge lists are scale-invariant) ----
    for (int r = 0; r < 3; r++) {
        const int* ei  = (r == 0) ? ei_buys : (r == 1 ? ei_rev : ei_follows);
        const int* src = ei;
        const int* dst = ei + E;
        int* offr = OFF + r * (NN_MAX + 1);
        cudaMemsetAsync(DEG, 0, (size_t)Nn * sizeof(int));
        hist_k<<<eg_blocks, 256>>>(dst, E, DEG);
        scan_k<<<1, 1024>>>(DEG, offr, Nn);
        cudaMemcpyAsync(DEG, offr, (size_t)Nn * sizeof(int), cudaMemcpyDeviceToDevice);
        scatter_k<<<eg_blocks, 256>>>(src, dst, E, DEG, CSRC + (size_t)r * E_MAX);
    }

    // ---- 6 relation-scale passes ----
    for (int rs = 0; rs < 6; rs++) {
        int r     = rs >> 1;   // relation 0..2
        int scale = rs & 1;    // 0 local, 1 global

        const float* Wsrc = (scale ? Wsg : Wsl) + (size_t)r * 128 * 128;
        const float* Wdst = (scale ? Wdg : Wdl) + (size_t)r * 128 * 128;
        const float* atts = (scale ? asg : asl) + (size_t)r * 128;
        const float* attd = (scale ? adg : adl) + (size_t)r * 128;
        const float* bias = (scale ? bg  : bl ) + (size_t)r * 128;
        float slope = scale ? 0.3f : 0.2f;

        const float* xs = (r == 1) ? x_item : x_user;
        const float* xd = (r == 0) ? x_item : x_user;

        float* target = (r == 0) ? (scale ? GLBI : LOCI) : (scale ? GLBU : LOCU);
        int beta = (r == 2) ? 1 : 0;
        const float* gates = (r == 0) ? nullptr : rg;
        int gidx = (r == 1) ? 0 : 1;
        int selfloop = (r == 2) ? 1 : 0;

        // HS projection + fused a_s dot
        gemm128<<<gemm_blocks, 256, GEMM_SMEM>>>(xs, Wsrc, HS, Nn, nullptr, 0, 0,
                                                 atts, AS, nullptr, nullptr, nullptr);
        // HD projection: only a_d needed -> skip the C store
        gemm128<<<gemm_blocks, 256, GEMM_SMEM>>>(xd, Wdst, nullptr, Nn, nullptr, 0, 0,
                                                 attd, AD, nullptr, nullptr, nullptr);

        gat_gather_k<<<gw_blocks, 256>>>(OFF + r * (NN_MAX + 1),
                                         CSRC + (size_t)r * E_MAX,
                                         AS, AD, HS, bias, target, beta,
                                         gates, gidx, selfloop, slope, Nn);
    }

    // ---- gated fusion + output GEMM, per node type ----
    float* out_f = (float*)d_out;
    for (int set = 0; set < 2; set++) {
        float* loc = set ? LOCI : LOCU;
        float* glb = set ? GLBI : GLBU;
        float* dsto = out_f + (size_t)set * Nn * HIDD;
        const float* gWtop = gW + (size_t)set * 256 * 128;
        const float* gWbot = gWtop + 128 * 128;
        const float* gbias = gb + (size_t)set * 128;
        const float* oWs   = oW + (size_t)set * 128 * 128;

        gemm128<<<gemm_blocks, 256, GEMM_SMEM>>>(loc, gWtop, TMP, Nn, nullptr, 0, 0,
                                                 nullptr, nullptr, nullptr, nullptr, nullptr);
        gemm128<<<gemm_blocks, 256, GEMM_SMEM>>>(glb, gWbot, TMP, Nn, gbias, 1, 1,
                                                 nullptr, nullptr, loc, glb, FUS);
        gemm128<<<gemm_blocks, 256, GEMM_SMEM>>>(FUS, oWs, dsto, Nn, nullptr, 0, 0,
                                                 nullptr, nullptr, nullptr, nullptr, nullptr);
    }
}

// round 9
// speedup vs baseline: 1.2116x; 1.2116x over previous
#include <cuda_runtime.h>
#include <cuda_bf16.h>
#include <cstdint>

// ---------------------------------------------------------------------------
// MultiScaleHeteroConv: 3 relations x 2 scales GAT + gated fusion.
// R9: HD projections eliminated -- a_d[n,h] = x[n,:] @ v_d where
//     v_d[k,h] = sum_c Wd[k,h*32+c]*att_d[h,c] is precomputed per pass.
//     Removes 6 of 18 GEMMs; replaced by two 51MB sweeps (ad_all_k).
//     GEMM = R3 f32x2 path; edge = R8 CSR gather (both passing).
// ---------------------------------------------------------------------------

#define NN_MAX 100000
#define E_MAX  1000000
#define HIDD   128
#define NHEAD  4

// -------------------- scratch (static device globals; no allocs) -----------
__device__ float g_HS  [(size_t)NN_MAX * HIDD];
__device__ float g_TMP [(size_t)NN_MAX * HIDD];
__device__ float g_LOCU[(size_t)NN_MAX * HIDD];
__device__ float g_GLBU[(size_t)NN_MAX * HIDD];
__device__ float g_LOCI[(size_t)NN_MAX * HIDD];
__device__ float g_GLBI[(size_t)NN_MAX * HIDD];
__device__ float g_FUS [(size_t)NN_MAX * HIDD];
__device__ float g_AS  [(size_t)NN_MAX * NHEAD];
__device__ float g_AD  [6 * (size_t)NN_MAX * NHEAD];   // a_d for all 6 passes
__device__ float g_VD  [24 * HIDD];                    // v_d vectors (6 passes x 4 heads)
__device__ int   g_DEG [NN_MAX];
__device__ int   g_OFF [3 * (NN_MAX + 1)];
__device__ int   g_CSRC[3 * E_MAX];

// -------------------- f32x2 helpers ----------------------------------------
__device__ __forceinline__ unsigned long long pack2(float lo, float hi) {
    unsigned long long d;
    asm("mov.b64 %0, {%1, %2};" : "=l"(d) : "r"(__float_as_uint(lo)), "r"(__float_as_uint(hi)));
    return d;
}
__device__ __forceinline__ void unpack2(unsigned long long d, float& lo, float& hi) {
    unsigned int a, b;
    asm("mov.b64 {%0, %1}, %2;" : "=r"(a), "=r"(b) : "l"(d));
    lo = __uint_as_float(a); hi = __uint_as_float(b);
}
#define FMA2(acc, a, b) \
    asm("fma.rn.f32x2 %0, %1, %2, %0;" : "+l"(acc) : "l"(a), "l"(b))

// -------------------- GEMM: C[M,128] = A[M,128] @ B[128,128] ----------------
__global__ __launch_bounds__(256, 1) void gemm128(
    const float* __restrict__ A, const float* __restrict__ B,
    float* __restrict__ Cw, int M,
    const float* __restrict__ bias, int beta, int act,
    const float* __restrict__ att, float* __restrict__ aout,
    const float* __restrict__ loc, const float* __restrict__ glb,
    float* __restrict__ fus)
{
    extern __shared__ float sm[];
    float* As = sm;               // [128][128]
    float* Bs = sm + 128 * 128;   // [128][128]
    int t  = threadIdx.x;
    int m0 = blockIdx.x * 128;

    const float4* B4 = (const float4*)B;
    float4* Bs4 = (float4*)Bs;
#pragma unroll
    for (int i = 0; i < 16; i++) Bs4[t + i * 256] = B4[t + i * 256];

    float4* As4 = (float4*)As;
#pragma unroll
    for (int i = 0; i < 16; i++) {
        int idx = t + i * 256;
        int row = idx >> 5;
        float4 v = make_float4(0.f, 0.f, 0.f, 0.f);
        if (m0 + row < M) v = ((const float4*)A)[(size_t)(m0 + row) * 32 + (idx & 31)];
        As4[idx] = v;
    }
    __syncthreads();

    int tx = t & 15, ty = t >> 4;
    unsigned long long acc[8][4];
#pragma unroll
    for (int r = 0; r < 8; r++)
#pragma unroll
        for (int c = 0; c < 4; c++) acc[r][c] = 0ull;

    const float* ap = As + (ty * 8) * 128;
    const float* bp = Bs + tx * 8;

#pragma unroll 2
    for (int k0 = 0; k0 < 128; k0 += 4) {
        float4 a4[8];
#pragma unroll
        for (int r = 0; r < 8; r++) a4[r] = *(const float4*)(ap + r * 128 + k0);
#pragma unroll
        for (int kk = 0; kk < 4; kk++) {
            const float* brow = bp + (k0 + kk) * 128;
            ulonglong2 p0 = *(const ulonglong2*)brow;
            ulonglong2 p1 = *(const ulonglong2*)(brow + 4);
            unsigned long long bq[4] = {p0.x, p0.y, p1.x, p1.y};
#pragma unroll
            for (int r = 0; r < 8; r++) {
                float av = (kk == 0) ? a4[r].x : (kk == 1) ? a4[r].y
                         : (kk == 2) ? a4[r].z : a4[r].w;
                unsigned long long ap2 = pack2(av, av);
#pragma unroll
                for (int c = 0; c < 4; c++) FMA2(acc[r][c], ap2, bq[c]);
            }
        }
    }

    float at[8];
    if (att) {
#pragma unroll
        for (int c = 0; c < 8; c++) at[c] = att[tx * 8 + c];
    }
#pragma unroll
    for (int r = 0; r < 8; r++) {
        int row = m0 + ty * 8 + r;
        bool valid = row < M;
        size_t base = (size_t)row * 128 + tx * 8;
        float v[8];
#pragma unroll
        for (int c = 0; c < 4; c++) unpack2(acc[r][c], v[2 * c], v[2 * c + 1]);
        if (beta && valid) {
            float4 o0 = *(const float4*)(Cw + base);
            float4 o1 = *(const float4*)(Cw + base + 4);
            v[0] += o0.x; v[1] += o0.y; v[2] += o0.z; v[3] += o0.w;
            v[4] += o1.x; v[5] += o1.y; v[6] += o1.z; v[7] += o1.w;
        }
        if (bias) {
#pragma unroll
            for (int c = 0; c < 8; c++) v[c] += bias[tx * 8 + c];
        }
        if (act) {
#pragma unroll
            for (int c = 0; c < 8; c++) v[c] = 1.f / (1.f + __expf(-v[c]));
        }
        if (fus) {
            if (valid) {
                float4 l0 = *(const float4*)(loc + base);
                float4 l1 = *(const float4*)(loc + base + 4);
                float4 g0 = *(const float4*)(glb + base);
                float4 g1 = *(const float4*)(glb + base + 4);
                float lv[8] = {l0.x, l0.y, l0.z, l0.w, l1.x, l1.y, l1.z, l1.w};
                float gv[8] = {g0.x, g0.y, g0.z, g0.w, g1.x, g1.y, g1.z, g1.w};
                float o[8];
#pragma unroll
                for (int c = 0; c < 8; c++) o[c] = v[c] * lv[c] + (1.f - v[c]) * gv[c];
                *(float4*)(fus + base)     = make_float4(o[0], o[1], o[2], o[3]);
                *(float4*)(fus + base + 4) = make_float4(o[4], o[5], o[6], o[7]);
            }
        } else if (Cw && valid) {
            *(float4*)(Cw + base)     = make_float4(v[0], v[1], v[2], v[3]);
            *(float4*)(Cw + base + 4) = make_float4(v[4], v[5], v[6], v[7]);
        }
        if (att) {
            float s = 0.f;
#pragma unroll
            for (int c = 0; c < 8; c++) s = fmaf(v[c], at[c], s);
            s += __shfl_xor_sync(0xffffffffu, s, 1);
            s += __shfl_xor_sync(0xffffffffu, s, 2);
            if ((tx & 3) == 0 && valid) aout[(size_t)row * 4 + (tx >> 2)] = s;
        }
    }
}

// -------------------- v_d precompute ----------------------------------------
// vd[(rs*4+h)*128 + k] = sum_c Wd_rs[k][h*32+c] * att_d_rs[h][c]
__global__ void prep_vd_k(const float* __restrict__ Wdl, const float* __restrict__ Wdg,
                          const float* __restrict__ adl, const float* __restrict__ adg,
                          float* __restrict__ VD)
{
    int idx = blockIdx.x * blockDim.x + threadIdx.x;   // 24*128
    if (idx >= 24 * 128) return;
    int j = idx >> 7, k = idx & 127;
    int rs = j >> 2, h = j & 3;
    int r = rs >> 1, scale = rs & 1;
    const float* Wd  = (scale ? Wdg : Wdl) + (size_t)r * 16384;
    const float* att = (scale ? adg : adl) + (size_t)r * 128 + h * 32;
    const float* wrow = Wd + (size_t)k * 128 + h * 32;
    float s = 0.f;
#pragma unroll
    for (int c = 0; c < 32; c++) s = fmaf(wrow[c], att[c], s);
    VD[idx] = s;
}

// -------------------- a_d for all passes of one node type -------------------
// One warp per node; x row read once; np passes (pass ids in p0..p3).
__global__ __launch_bounds__(256) void ad_all_k(
    const float* __restrict__ x, const float* __restrict__ VD,
    float* __restrict__ AD, int n, int np, int p0, int p1, int p2, int p3)
{
    __shared__ float svd[24 * 128];
    int t = threadIdx.x;
    for (int i = t; i < 24 * 128; i += 256) svd[i] = VD[i];
    __syncthreads();

    int w = (blockIdx.x * 256 + t) >> 5;
    int lane = t & 31;
    if (w >= n) return;
    float4 x4 = *(const float4*)(x + (size_t)w * HIDD + lane * 4);

    int pid[4] = {p0, p1, p2, p3};
#pragma unroll 4
    for (int pi = 0; pi < 4; pi++) {
        if (pi >= np) break;
        int rs = pid[pi];
#pragma unroll
        for (int h = 0; h < 4; h++) {
            const float* vd = svd + (rs * 4 + h) * 128 + lane * 4;
            float s = x4.x * vd[0] + x4.y * vd[1] + x4.z * vd[2] + x4.w * vd[3];
            s += __shfl_xor_sync(0xffffffffu, s, 16);
            s += __shfl_xor_sync(0xffffffffu, s, 8);
            s += __shfl_xor_sync(0xffffffffu, s, 4);
            s += __shfl_xor_sync(0xffffffffu, s, 2);
            s += __shfl_xor_sync(0xffffffffu, s, 1);
            if (lane == 0) AD[(size_t)rs * NN_MAX * 4 + (size_t)w * 4 + h] = s;
        }
    }
}

// -------------------- CSR build ---------------------------------------------
__global__ void hist_k(const int* __restrict__ dst, int nE, int* __restrict__ deg)
{
    int e = blockIdx.x * blockDim.x + threadIdx.x;
    if (e < nE) atomicAdd(&deg[dst[e]], 1);
}

__global__ __launch_bounds__(1024) void scan_k(const int* __restrict__ deg,
                                               int* __restrict__ off, int n)
{
    __shared__ int ssum[1024];
    int t = threadIdx.x;
    int chunk = (n + 1023) / 1024;
    int start = t * chunk;
    int end   = start + chunk; if (end > n) end = n;
    int s = 0;
    for (int i = start; i < end; i++) s += deg[i];
    ssum[t] = s;
    __syncthreads();
    for (int o = 1; o < 1024; o <<= 1) {
        int u = (t >= o) ? ssum[t - o] : 0;
        __syncthreads();
        ssum[t] += u;
        __syncthreads();
    }
    int running = (t == 0) ? 0 : ssum[t - 1];
    for (int i = start; i < end; i++) { off[i] = running; running += deg[i]; }
    if (t == 1023) off[n] = ssum[1023];
}

__global__ void scatter_k(const int* __restrict__ src, const int* __restrict__ dst,
                          int nE, int* __restrict__ cur, int* __restrict__ csrc)
{
    int e = blockIdx.x * blockDim.x + threadIdx.x;
    if (e >= nE) return;
    int pos = atomicAdd(&cur[dst[e]], 1);
    csrc[pos] = src[e];
}

// -------------------- gather: one warp per dst node -------------------------
__global__ __launch_bounds__(256) void gat_gather_k(
    const int* __restrict__ off, const int* __restrict__ csrc,
    const float* __restrict__ a_s, const float* __restrict__ a_d,
    const float* __restrict__ HS, const float* __restrict__ bias,
    float* __restrict__ target, int beta,
    const float* __restrict__ gates, int gidx,
    int selfloop, float slope, int n)
{
    int w = (blockIdx.x * blockDim.x + threadIdx.x) >> 5;
    int lane = threadIdx.x & 31;
    if (w >= n) return;
    int d = w, h = lane >> 3;

    float adh = a_d[(size_t)d * 4 + h];
    float a0 = 0.f, a1 = 0.f, a2 = 0.f, a3 = 0.f, den = 0.f;

    int i0 = off[d], i1 = off[d + 1];
    for (int i = i0; i < i1; i++) {
        int s = csrc[i];
        float e = a_s[(size_t)s * 4 + h] + adh;
        e = e > 0.f ? e : e * slope;
        float wt = __expf(e);
        float4 hv = *(const float4*)(HS + (size_t)s * HIDD + lane * 4);
        a0 = fmaf(wt, hv.x, a0); a1 = fmaf(wt, hv.y, a1);
        a2 = fmaf(wt, hv.z, a2); a3 = fmaf(wt, hv.w, a3);
        den += wt;
    }
    if (selfloop) {
        float e = a_s[(size_t)d * 4 + h] + adh;
        e = e > 0.f ? e : e * slope;
        float wt = __expf(e);
        float4 hv = *(const float4*)(HS + (size_t)d * HIDD + lane * 4);
        a0 = fmaf(wt, hv.x, a0); a1 = fmaf(wt, hv.y, a1);
        a2 = fmaf(wt, hv.z, a2); a3 = fmaf(wt, hv.w, a3);
        den += wt;
    }

    float coef = 1.f;
    if (gates) {
        float g0 = gates[0], g1 = gates[1];
        float mx = fmaxf(g0, g1);
        float e0 = __expf(g0 - mx), e1 = __expf(g1 - mx);
        coef = (gidx == 0 ? e0 : e1) / (e0 + e1);
    }
    float inv = 1.f / (den + 1e-16f);
    float4 bv = *(const float4*)(bias + lane * 4);
    float4 o;
    o.x = coef * (a0 * inv + bv.x);
    o.y = coef * (a1 * inv + bv.y);
    o.z = coef * (a2 * inv + bv.z);
    o.w = coef * (a3 * inv + bv.w);
    float* tp = target + (size_t)d * HIDD + lane * 4;
    if (beta) {
        float4 old = *(const float4*)tp;
        o.x += old.x; o.y += old.y; o.z += old.z; o.w += old.w;
    }
    *(float4*)tp = o;
}

// ---------------------------------------------------------------------------
extern "C" void kernel_launch(void* const* d_in, const int* in_sizes, int n_in,
                              void* d_out, int out_size)
{
    const float* x_user = (const float*)d_in[0];
    const float* x_item = (const float*)d_in[1];
    const float* Wsl    = (const float*)d_in[2];
    const float* Wdl    = (const float*)d_in[3];
    const float* asl    = (const float*)d_in[4];
    const float* adl    = (const float*)d_in[5];
    const float* bl     = (const float*)d_in[6];
    const float* Wsg    = (const float*)d_in[7];
    const float* Wdg    = (const float*)d_in[8];
    const float* asg    = (const float*)d_in[9];
    const float* adg    = (const float*)d_in[10];
    const float* bg     = (const float*)d_in[11];
    const float* gW     = (const float*)d_in[12];
    const float* gb     = (const float*)d_in[13];
    const float* oW     = (const float*)d_in[14];
    const float* rg     = (const float*)d_in[15];
    const int*   ei_buys    = (const int*)d_in[16];
    const int*   ei_rev     = (const int*)d_in[17];
    const int*   ei_follows = (const int*)d_in[18];

    int Nn = in_sizes[0] / HIDD;
    int E  = in_sizes[16] / 2;

    float *HS, *TMP, *LOCU, *GLBU, *LOCI, *GLBI, *FUS, *AS, *AD, *VD;
    int *DEG, *OFF, *CSRC;
    cudaGetSymbolAddress((void**)&HS,  g_HS);
    cudaGetSymbolAddress((void**)&TMP, g_TMP);
    cudaGetSymbolAddress((void**)&LOCU,g_LOCU);
    cudaGetSymbolAddress((void**)&GLBU,g_GLBU);
    cudaGetSymbolAddress((void**)&LOCI,g_LOCI);
    cudaGetSymbolAddress((void**)&GLBI,g_GLBI);
    cudaGetSymbolAddress((void**)&FUS, g_FUS);
    cudaGetSymbolAddress((void**)&AS,  g_AS);
    cudaGetSymbolAddress((void**)&AD,  g_AD);
    cudaGetSymbolAddress((void**)&VD,  g_VD);
    cudaGetSymbolAddress((void**)&DEG, g_DEG);
    cudaGetSymbolAddress((void**)&OFF, g_OFF);
    cudaGetSymbolAddress((void**)&CSRC,g_CSRC);

    const int GEMM_SMEM = (128 * 128 + 128 * 128) * (int)sizeof(float);  // 128KB
    cudaFuncSetAttribute(gemm128, cudaFuncAttributeMaxDynamicSharedMemorySize, GEMM_SMEM);

    int gemm_blocks = (Nn + 127) / 128;
    int eg_blocks   = (E + 255) / 256;
    int gw_blocks   = (Nn * 32 + 255) / 256;

    // ---- build 3 CSRs ----
    for (int r = 0; r < 3; r++) {
        const int* ei  = (r == 0) ? ei_buys : (r == 1 ? ei_rev : ei_follows);
        const int* src = ei;
        const int* dst = ei + E;
        int* offr = OFF + r * (NN_MAX + 1);
        cudaMemsetAsync(DEG, 0, (size_t)Nn * sizeof(int));
        hist_k<<<eg_blocks, 256>>>(dst, E, DEG);
        scan_k<<<1, 1024>>>(DEG, offr, Nn);
        cudaMemcpyAsync(DEG, offr, (size_t)Nn * sizeof(int), cudaMemcpyDeviceToDevice);
        scatter_k<<<eg_blocks, 256>>>(src, dst, E, DEG, CSRC + (size_t)r * E_MAX);
    }

    // ---- precompute v_d, then all a_d with two x sweeps ----
    prep_vd_k<<<(24 * 128 + 255) / 256, 256>>>(Wdl, Wdg, adl, adg, VD);
    // x_item is dst for passes 0,1 (r=0); x_user for passes 2..5 (r=1,2)
    ad_all_k<<<gw_blocks, 256>>>(x_item, VD, AD, Nn, 2, 0, 1, 0, 0);
    ad_all_k<<<gw_blocks, 256>>>(x_user, VD, AD, Nn, 4, 2, 3, 4, 5);

    // ---- 6 relation-scale passes ----
    for (int rs = 0; rs < 6; rs++) {
        int r     = rs >> 1;
        int scale = rs & 1;

        const float* Wsrc = (scale ? Wsg : Wsl) + (size_t)r * 128 * 128;
        const float* atts = (scale ? asg : asl) + (size_t)r * 128;
        const float* bias = (scale ? bg  : bl ) + (size_t)r * 128;
        float slope = scale ? 0.3f : 0.2f;

        const float* xs = (r == 1) ? x_item : x_user;

        float* target = (r == 0) ? (scale ? GLBI : LOCI) : (scale ? GLBU : LOCU);
        int beta = (r == 2) ? 1 : 0;
        const float* gates = (r == 0) ? nullptr : rg;
        int gidx = (r == 1) ? 0 : 1;
        int selfloop = (r == 2) ? 1 : 0;

        // HS projection + fused a_s dot (a_d comes from ad_all_k)
        gemm128<<<gemm_blocks, 256, GEMM_SMEM>>>(xs, Wsrc, HS, Nn, nullptr, 0, 0,
                                                 atts, AS, nullptr, nullptr, nullptr);

        gat_gather_k<<<gw_blocks, 256>>>(OFF + r * (NN_MAX + 1),
                                         CSRC + (size_t)r * E_MAX,
                                         AS, AD + (size_t)rs * NN_MAX * 4,
                                         HS, bias, target, beta,
                                         gates, gidx, selfloop, slope, Nn);
    }

    // ---- gated fusion + output GEMM, per node type ----
    float* out_f = (float*)d_out;
    for (int set = 0; set < 2; set++) {
        float* loc = set ? LOCI : LOCU;
        float* glb = set ? GLBI : GLBU;
        float* dsto = out_f + (size_t)set * Nn * HIDD;
        const float* gWtop = gW + (size_t)set * 256 * 128;
        const float* gWbot = gWtop + 128 * 128;
        const float* gbias = gb + (size_t)set * 128;
        const float* oWs   = oW + (size_t)set * 128 * 128;

        gemm128<<<gemm_blocks, 256, GEMM_SMEM>>>(loc, gWtop, TMP, Nn, nullptr, 0, 0,
                                                 nullptr, nullptr, nullptr, nullptr, nullptr);
        gemm128<<<gemm_blocks, 256, GEMM_SMEM>>>(glb, gWbot, TMP, Nn, gbias, 1, 1,
                                                 nullptr, nullptr, loc, glb, FUS);
        gemm128<<<gemm_blocks, 256, GEMM_SMEM>>>(FUS, oWs, dsto, Nn, nullptr, 0, 0,
                                                 nullptr, nullptr, nullptr, nullptr, nullptr);
    }
}